// round 15
// baseline (speedup 1.0000x reference)
#include <cuda_runtime.h>
#include <cuda_fp16.h>

#define MAXN  100000
#define MAXE  600000
#define NG    512
#define H     128
#define NVOC  4096

// ---- scratch (static __device__ globals; zero-initialized at load,
//      and every replay leaves them re-zeroed / overwritten) ----
__device__ int   g_deg[MAXN];       // re-zeroed by k_conv1
__device__ int   g_cursor[MAXN];    // overwritten by k_scanC each replay
__device__ int   g_rowptr[MAXN + 1];
__device__ uint2 g_edge[MAXE];      // {src | x[src]<<17, bits(dis[src])}
__device__ float g_dis[MAXN];
__device__ uint2 g_embW1h[NVOC * 32];           // fp16 table, 1 MB
__device__ uint2 g_h1h[(size_t)MAXN * 32];      // fp16 h1, 25.6 MB
__device__ float g_gsum[NG * H];    // re-zeroed by k_final after read
__device__ int   g_gcnt[NG];        // re-zeroed by k_final after read
__device__ int   g_bsum[128];

// ---- fused: embW1 = emb @ W1 (blocks 0-511)  +  degree/graph count (512-1023) ----
__global__ void k_prepcount(const float* __restrict__ emb, const float* __restrict__ W1,
                            const int* __restrict__ dst, int E,
                            const int* __restrict__ batch, int N) {
    __shared__ int hist[NG];
    int b = blockIdx.x;
    if (b < 512) {
        int j = threadIdx.x;
        int r0 = b * 8;
        __half* T = (__half*)g_embW1h;
        for (int r = r0; r < r0 + 8; r++) {
            const float* er = emb + (size_t)r * H;
            float acc = 0.f;
#pragma unroll 8
            for (int k = 0; k < H; k++) acc = fmaf(__ldg(er + k), W1[k * H + j], acc);
            T[(size_t)r * H + j] = __float2half_rn(acc);
        }
    } else {
        int bc = b - 512;
        for (int i = threadIdx.x; i < NG; i += 128) hist[i] = 0;
        __syncthreads();
        int i0 = bc * 128 + threadIdx.x;
        int stride = 512 * 128;
        for (int e = i0; e < E; e += stride) atomicAdd(&g_deg[dst[e]], 1);
        for (int v = i0; v < N; v += stride) atomicAdd(&hist[batch[v]], 1);
        __syncthreads();
        for (int i = threadIdx.x; i < NG; i += 128)
            if (hist[i]) atomicAdd(&g_gcnt[i], hist[i]);
    }
}

// ---- scan phase A: per-block sums (shuffle reduce) ----
__global__ void k_scanA(int N) {
    __shared__ int wsum[32];
    int t = threadIdx.x;
    int i = blockIdx.x * 1024 + t;
    int v = (i < N) ? g_deg[i] : 0;
#pragma unroll
    for (int off = 16; off; off >>= 1) v += __shfl_down_sync(0xFFFFFFFFu, v, off);
    int wid = t >> 5, lane = t & 31;
    if (lane == 0) wsum[wid] = v;
    __syncthreads();
    if (wid == 0) {
        int s = wsum[lane];
#pragma unroll
        for (int off = 16; off; off >>= 1) s += __shfl_down_sync(0xFFFFFFFFu, s, off);
        if (lane == 0) g_bsum[blockIdx.x] = s;
    }
}

// ---- scan phase C: shuffle scan; deg -> rowptr (+cursor), dis ----
__global__ void k_scanC(int N, int E) {
    __shared__ int wtot[32];
    __shared__ int sprefix;
    int t = threadIdx.x, b = blockIdx.x;
    if (t == 0) sprefix = 0;
    int lane = t & 31, wid = t >> 5;
    int i = b * 1024 + t;
    int v = (i < N) ? g_deg[i] : 0;
    int val = v;
#pragma unroll
    for (int off = 1; off < 32; off <<= 1) {
        int n = __shfl_up_sync(0xFFFFFFFFu, val, off);
        if (lane >= off) val += n;
    }
    if (lane == 31) wtot[wid] = val;
    __syncthreads();               // orders sprefix=0 and wtot before use
    if (t < b) atomicAdd(&sprefix, g_bsum[t]);   // b <= 97
    if (wid == 0) {
        int wv = wtot[lane];
        int ws = wv;
#pragma unroll
        for (int off = 1; off < 32; off <<= 1) {
            int n = __shfl_up_sync(0xFFFFFFFFu, ws, off);
            if (lane >= off) ws += n;
        }
        wtot[lane] = ws - wv;      // exclusive warp offsets
    }
    __syncthreads();
    if (i < N) {
        int incl = val + wtot[wid];
        int rp = sprefix + incl - v;
        g_rowptr[i] = rp;
        g_cursor[i] = rp;                        // fill's allocator starts here
        g_dis[i] = rsqrtf((float)(v + 1));       // +1 self-loop
    }
    if (i == 0) g_rowptr[N] = E;
}

// ---- fill CSR: packed 8B record, single allocator atomic ----
__global__ void k_fill(const int* __restrict__ src, const int* __restrict__ dst,
                       const int* __restrict__ x, int E) {
    int i0 = blockIdx.x * blockDim.x + threadIdx.x;
    int stride = gridDim.x * blockDim.x;
    for (int e = i0; e < E; e += stride) {
        int d = dst[e];
        int s = src[e];
        int idx = atomicAdd(&g_cursor[d], 1);
        uint2 rec;
        rec.x = (unsigned)s | ((unsigned)x[s] << 17);   // src:17b | x:12b
        rec.y = __float_as_uint(g_dis[s]);
        g_edge[idx] = rec;
    }
}

__device__ __forceinline__ void fma_row(uint2 u, float w,
                                        float& ax, float& ay, float& az, float& aw) {
    float2 f0 = __half22float2(*(__half2*)&u.x);
    float2 f1 = __half22float2(*(__half2*)&u.y);
    ax = fmaf(w, f0.x, ax); ay = fmaf(w, f0.y, ay);
    az = fmaf(w, f1.x, az); aw = fmaf(w, f1.y, aw);
}

// ---- conv1: warp per node, predicated 4-wide edge groups; re-zeroes deg ----
__global__ void k_conv1(const int* __restrict__ x, const float* __restrict__ b1, int N) {
    int v = (blockIdx.x * blockDim.x + threadIdx.x) >> 5;
    int lane = threadIdx.x & 31;
    if (v >= N) return;
    float dv = g_dis[v];
    const uint2* T = g_embW1h;

    uint2 us = __ldg(&T[(size_t)__ldg(x + v) * 32 + lane]);
    float ax = 0.f, ay = 0.f, az = 0.f, aw = 0.f;
    fma_row(us, dv * dv, ax, ay, az, aw);

    int e0 = g_rowptr[v], e1 = g_rowptr[v + 1];
    int last = e1 - 1;
    for (int e = e0; e < e1; e += 4) {
        int i0 = min(e,     last), i1 = min(e + 1, last);
        int i2 = min(e + 2, last), i3 = min(e + 3, last);
        uint2 r0 = __ldg(&g_edge[i0]);
        uint2 r1 = __ldg(&g_edge[i1]);
        uint2 r2 = __ldg(&g_edge[i2]);
        uint2 r3 = __ldg(&g_edge[i3]);
        float w0 = (e     < e1) ? dv * __uint_as_float(r0.y) : 0.f;
        float w1 = (e + 1 < e1) ? dv * __uint_as_float(r1.y) : 0.f;
        float w2 = (e + 2 < e1) ? dv * __uint_as_float(r2.y) : 0.f;
        float w3 = (e + 3 < e1) ? dv * __uint_as_float(r3.y) : 0.f;
        uint2 u0 = __ldg(&T[(size_t)(r0.x >> 17) * 32 + lane]);
        uint2 u1 = __ldg(&T[(size_t)(r1.x >> 17) * 32 + lane]);
        uint2 u2 = __ldg(&T[(size_t)(r2.x >> 17) * 32 + lane]);
        uint2 u3 = __ldg(&T[(size_t)(r3.x >> 17) * 32 + lane]);
        fma_row(u0, w0, ax, ay, az, aw);
        fma_row(u1, w1, ax, ay, az, aw);
        fma_row(u2, w2, ax, ay, az, aw);
        fma_row(u3, w3, ax, ay, az, aw);
    }
    float4 bb = ((const float4*)b1)[lane];
    float ox = fmaxf(ax + bb.x, 0.f), oy = fmaxf(ay + bb.y, 0.f);
    float oz = fmaxf(az + bb.z, 0.f), ow = fmaxf(aw + bb.w, 0.f);
    __half2 p0 = __floats2half2_rn(ox, oy);
    __half2 p1 = __floats2half2_rn(oz, ow);
    uint2 o;
    o.x = *(unsigned*)&p0; o.y = *(unsigned*)&p1;
    g_h1h[(size_t)v * 32 + lane] = o;
    if (lane == 0) g_deg[v] = 0;      // re-zero for next replay
}

// ---- conv2 + pooling: warp per NPW=16 node run (batch sorted) ----
__global__ void k_conv2pool(const int* __restrict__ batch, int N) {
    const int NPW = 16;
    int gw = (blockIdx.x * blockDim.x + threadIdx.x) >> 5;
    int lane = threadIdx.x & 31;
    int v0 = gw * NPW;
    if (v0 >= N) return;
    int v1 = min(v0 + NPW, N);
    const uint2* Hm = g_h1h;

    float gx = 0.f, gy = 0.f, gz = 0.f, gwv = 0.f;
    int curg = -1;
    for (int v = v0; v < v1; v++) {
        float dv = g_dis[v];
        float nx = 0.f, ny = 0.f, nz = 0.f, nw = 0.f;
        uint2 us = __ldg(&Hm[(size_t)v * 32 + lane]);
        fma_row(us, dv * dv, nx, ny, nz, nw);
        int e0 = g_rowptr[v], e1 = g_rowptr[v + 1];
        int last = e1 - 1;
        for (int e = e0; e < e1; e += 4) {
            int i0 = min(e,     last), i1 = min(e + 1, last);
            int i2 = min(e + 2, last), i3 = min(e + 3, last);
            uint2 r0 = __ldg(&g_edge[i0]);
            uint2 r1 = __ldg(&g_edge[i1]);
            uint2 r2 = __ldg(&g_edge[i2]);
            uint2 r3 = __ldg(&g_edge[i3]);
            float w0 = (e     < e1) ? dv * __uint_as_float(r0.y) : 0.f;
            float w1 = (e + 1 < e1) ? dv * __uint_as_float(r1.y) : 0.f;
            float w2 = (e + 2 < e1) ? dv * __uint_as_float(r2.y) : 0.f;
            float w3 = (e + 3 < e1) ? dv * __uint_as_float(r3.y) : 0.f;
            uint2 u0 = __ldg(&Hm[(size_t)(r0.x & 0x1FFFFu) * 32 + lane]);
            uint2 u1 = __ldg(&Hm[(size_t)(r1.x & 0x1FFFFu) * 32 + lane]);
            uint2 u2 = __ldg(&Hm[(size_t)(r2.x & 0x1FFFFu) * 32 + lane]);
            uint2 u3 = __ldg(&Hm[(size_t)(r3.x & 0x1FFFFu) * 32 + lane]);
            fma_row(u0, w0, nx, ny, nz, nw);
            fma_row(u1, w1, nx, ny, nz, nw);
            fma_row(u2, w2, nx, ny, nz, nw);
            fma_row(u3, w3, nx, ny, nz, nw);
        }
        int g = batch[v];
        if (g != curg) {
            if (curg >= 0) {
                float* p = g_gsum + curg * H + lane * 4;
                atomicAdd(p, gx); atomicAdd(p + 1, gy);
                atomicAdd(p + 2, gz); atomicAdd(p + 3, gwv);
            }
            curg = g; gx = nx; gy = ny; gz = nz; gwv = nw;
        } else {
            gx += nx; gy += ny; gz += nz; gwv += nw;
        }
    }
    if (curg >= 0) {
        float* p = g_gsum + curg * H + lane * 4;
        atomicAdd(p, gx); atomicAdd(p + 1, gy);
        atomicAdd(p + 2, gz); atomicAdd(p + 3, gwv);
    }
}

// ---- final: out[g] = (gsum[g] @ W2) / cnt[g] + b2 ; re-zeroes gsum/gcnt ----
__global__ void k_final(const float* __restrict__ W2, const float* __restrict__ b2,
                        float* __restrict__ out) {
    __shared__ float srow[H];
    int g = blockIdx.x, j = threadIdx.x;
    srow[j] = g_gsum[g * H + j];
    int c = g_gcnt[g];
    __syncthreads();
    g_gsum[g * H + j] = 0.f;          // re-zero for next replay
    if (j == 0) g_gcnt[g] = 0;
    float acc = 0.f;
#pragma unroll 8
    for (int k = 0; k < H; k++) acc = fmaf(srow[k], W2[k * H + j], acc);
    out[g * H + j] = (c > 0) ? (acc / (float)c + b2[j]) : 0.f;
}

extern "C" void kernel_launch(void* const* d_in, const int* in_sizes, int n_in,
                              void* d_out, int out_size) {
    const int*   x     = (const int*)d_in[0];
    const int*   ei    = (const int*)d_in[1];
    const int*   batch = (const int*)d_in[2];
    const float* emb   = (const float*)d_in[3];
    const float* W1    = (const float*)d_in[4];
    const float* b1    = (const float*)d_in[5];
    const float* W2    = (const float*)d_in[6];
    const float* b2    = (const float*)d_in[7];
    float* out = (float*)d_out;

    int N = in_sizes[0];
    int E = in_sizes[1] / 2;
    const int* src = ei;
    const int* dst = ei + E;

    k_prepcount<<<1024, 128>>>(emb, W1, dst, E, batch, N);
    int nb = (N + 1023) / 1024;
    k_scanA<<<nb, 1024>>>(N);
    k_scanC<<<nb, 1024>>>(N, E);
    k_fill<<<(E + 255) / 256, 256>>>(src, dst, x, E);
    k_conv1<<<((size_t)N * 32 + 255) / 256, 256>>>(x, b1, N);
    int w2n = (N + 15) / 16;
    k_conv2pool<<<((size_t)w2n * 32 + 255) / 256, 256>>>(batch, N);
    k_final<<<NG, H>>>(W2, b2, out);
}

// round 17
// speedup vs baseline: 1.1129x; 1.1129x over previous
#include <cuda_runtime.h>
#include <cuda_fp16.h>

#define MAXN  100000
#define MAXE  600000
#define NG    512
#define H     128
#define NVOC  4096

// ---- scratch (static __device__ globals; zero-initialized at load,
//      and every replay leaves them re-zeroed / overwritten) ----
__device__ int   g_deg[MAXN];       // re-zeroed by k_conv1
__device__ int   g_cursor[MAXN];    // overwritten by k_scanC each replay
__device__ int   g_rowptr[MAXN + 1];
__device__ uint2 g_edge[MAXE];      // {src | x[src]<<17, bits(dis[src])}
__device__ float g_dis[MAXN];
__device__ uint2 g_embW1h[NVOC * 32];           // fp16 table, 1 MB
__device__ uint2 g_h1h[(size_t)MAXN * 32];      // fp16 h1, 25.6 MB
__device__ float g_gsum[NG * H];    // re-zeroed by k_final after read
__device__ int   g_gcnt[NG];        // re-zeroed by k_final after read
__device__ int   g_bsum[128];

// ---- fused: embW1 = emb @ W1 (blocks 0-511)  +  degree/graph count (512-1023) ----
__global__ void k_prepcount(const float* __restrict__ emb, const float* __restrict__ W1,
                            const int* __restrict__ dst, int E,
                            const int* __restrict__ batch, int N) {
    __shared__ int hist[NG];
    int b = blockIdx.x;
    if (b < 512) {
        int j = threadIdx.x;
        int r0 = b * 8;
        __half* T = (__half*)g_embW1h;
        for (int r = r0; r < r0 + 8; r++) {
            const float* er = emb + (size_t)r * H;
            float acc = 0.f;
#pragma unroll 8
            for (int k = 0; k < H; k++) acc = fmaf(__ldg(er + k), W1[k * H + j], acc);
            T[(size_t)r * H + j] = __float2half_rn(acc);
        }
    } else {
        int bc = b - 512;
        for (int i = threadIdx.x; i < NG; i += 128) hist[i] = 0;
        __syncthreads();
        int i0 = bc * 128 + threadIdx.x;
        int stride = 512 * 128;
        for (int e = i0; e < E; e += stride) atomicAdd(&g_deg[dst[e]], 1);
        for (int v = i0; v < N; v += stride) atomicAdd(&hist[batch[v]], 1);
        __syncthreads();
        for (int i = threadIdx.x; i < NG; i += 128)
            if (hist[i]) atomicAdd(&g_gcnt[i], hist[i]);
    }
}

// ---- scan phase A: per-block sums (shuffle reduce) ----
__global__ void k_scanA(int N) {
    __shared__ int wsum[32];
    int t = threadIdx.x;
    int i = blockIdx.x * 1024 + t;
    int v = (i < N) ? g_deg[i] : 0;
#pragma unroll
    for (int off = 16; off; off >>= 1) v += __shfl_down_sync(0xFFFFFFFFu, v, off);
    int wid = t >> 5, lane = t & 31;
    if (lane == 0) wsum[wid] = v;
    __syncthreads();
    if (wid == 0) {
        int s = wsum[lane];
#pragma unroll
        for (int off = 16; off; off >>= 1) s += __shfl_down_sync(0xFFFFFFFFu, s, off);
        if (lane == 0) g_bsum[blockIdx.x] = s;
    }
}

// ---- scan phase C: shuffle scan; deg -> rowptr (+cursor), dis ----
__global__ void k_scanC(int N, int E) {
    __shared__ int wtot[32];
    __shared__ int sprefix;
    int t = threadIdx.x, b = blockIdx.x;
    if (t == 0) sprefix = 0;
    int lane = t & 31, wid = t >> 5;
    int i = b * 1024 + t;
    int v = (i < N) ? g_deg[i] : 0;
    int val = v;
#pragma unroll
    for (int off = 1; off < 32; off <<= 1) {
        int n = __shfl_up_sync(0xFFFFFFFFu, val, off);
        if (lane >= off) val += n;
    }
    if (lane == 31) wtot[wid] = val;
    __syncthreads();               // orders sprefix=0 and wtot before use
    if (t < b) atomicAdd(&sprefix, g_bsum[t]);   // b <= 97
    if (wid == 0) {
        int wv = wtot[lane];
        int ws = wv;
#pragma unroll
        for (int off = 1; off < 32; off <<= 1) {
            int n = __shfl_up_sync(0xFFFFFFFFu, ws, off);
            if (lane >= off) ws += n;
        }
        wtot[lane] = ws - wv;      // exclusive warp offsets
    }
    __syncthreads();
    if (i < N) {
        int incl = val + wtot[wid];
        int rp = sprefix + incl - v;
        g_rowptr[i] = rp;
        g_cursor[i] = rp;                        // fill's allocator starts here
        g_dis[i] = rsqrtf((float)(v + 1));       // +1 self-loop
    }
    if (i == 0) g_rowptr[N] = E;
}

// ---- fill CSR: packed 8B record, single allocator atomic ----
__global__ void k_fill(const int* __restrict__ src, const int* __restrict__ dst,
                       const int* __restrict__ x, int E) {
    int i0 = blockIdx.x * blockDim.x + threadIdx.x;
    int stride = gridDim.x * blockDim.x;
    for (int e = i0; e < E; e += stride) {
        int d = dst[e];
        int s = src[e];
        int idx = atomicAdd(&g_cursor[d], 1);
        uint2 rec;
        rec.x = (unsigned)s | ((unsigned)x[s] << 17);   // src:17b | x:12b
        rec.y = __float_as_uint(g_dis[s]);
        g_edge[idx] = rec;
    }
}

__device__ __forceinline__ void fma_row(uint2 u, float w,
                                        float& ax, float& ay, float& az, float& aw) {
    float2 f0 = __half22float2(*(__half2*)&u.x);
    float2 f1 = __half22float2(*(__half2*)&u.y);
    ax = fmaf(w, f0.x, ax); ay = fmaf(w, f0.y, ay);
    az = fmaf(w, f1.x, az); aw = fmaf(w, f1.y, aw);
}

// ---- conv1: warp per node, unroll 4 + serial remainder; re-zeroes deg ----
__global__ void k_conv1(const int* __restrict__ x, const float* __restrict__ b1, int N) {
    int v = (blockIdx.x * blockDim.x + threadIdx.x) >> 5;
    int lane = threadIdx.x & 31;
    if (v >= N) return;
    float dv = g_dis[v];
    const uint2* T = g_embW1h;

    uint2 us = __ldg(&T[(size_t)__ldg(x + v) * 32 + lane]);
    float ax = 0.f, ay = 0.f, az = 0.f, aw = 0.f;
    fma_row(us, dv * dv, ax, ay, az, aw);

    int e = g_rowptr[v], e1 = g_rowptr[v + 1];
    for (; e + 3 < e1; e += 4) {
        uint2 r0 = __ldg(&g_edge[e]);
        uint2 r1 = __ldg(&g_edge[e + 1]);
        uint2 r2 = __ldg(&g_edge[e + 2]);
        uint2 r3 = __ldg(&g_edge[e + 3]);
        uint2 u0 = __ldg(&T[(size_t)(r0.x >> 17) * 32 + lane]);
        uint2 u1 = __ldg(&T[(size_t)(r1.x >> 17) * 32 + lane]);
        uint2 u2 = __ldg(&T[(size_t)(r2.x >> 17) * 32 + lane]);
        uint2 u3 = __ldg(&T[(size_t)(r3.x >> 17) * 32 + lane]);
        fma_row(u0, dv * __uint_as_float(r0.y), ax, ay, az, aw);
        fma_row(u1, dv * __uint_as_float(r1.y), ax, ay, az, aw);
        fma_row(u2, dv * __uint_as_float(r2.y), ax, ay, az, aw);
        fma_row(u3, dv * __uint_as_float(r3.y), ax, ay, az, aw);
    }
    for (; e < e1; e++) {
        uint2 r0 = __ldg(&g_edge[e]);
        uint2 u0 = __ldg(&T[(size_t)(r0.x >> 17) * 32 + lane]);
        fma_row(u0, dv * __uint_as_float(r0.y), ax, ay, az, aw);
    }
    float4 bb = ((const float4*)b1)[lane];
    float ox = fmaxf(ax + bb.x, 0.f), oy = fmaxf(ay + bb.y, 0.f);
    float oz = fmaxf(az + bb.z, 0.f), ow = fmaxf(aw + bb.w, 0.f);
    __half2 p0 = __floats2half2_rn(ox, oy);
    __half2 p1 = __floats2half2_rn(oz, ow);
    uint2 o;
    o.x = *(unsigned*)&p0; o.y = *(unsigned*)&p1;
    g_h1h[(size_t)v * 32 + lane] = o;
    if (lane == 0) g_deg[v] = 0;      // re-zero for next replay
}

// ---- conv2 + pooling: warp per NPW=16 node run (batch sorted), unroll 4 ----
__global__ void k_conv2pool(const int* __restrict__ batch, int N) {
    const int NPW = 16;
    int gw = (blockIdx.x * blockDim.x + threadIdx.x) >> 5;
    int lane = threadIdx.x & 31;
    int v0 = gw * NPW;
    if (v0 >= N) return;
    int v1 = min(v0 + NPW, N);
    const uint2* Hm = g_h1h;

    float gx = 0.f, gy = 0.f, gz = 0.f, gwv = 0.f;
    int curg = -1;
    for (int v = v0; v < v1; v++) {
        float dv = g_dis[v];
        float nx = 0.f, ny = 0.f, nz = 0.f, nw = 0.f;
        uint2 us = __ldg(&Hm[(size_t)v * 32 + lane]);
        fma_row(us, dv * dv, nx, ny, nz, nw);
        int e = g_rowptr[v], e1 = g_rowptr[v + 1];
        for (; e + 3 < e1; e += 4) {
            uint2 r0 = __ldg(&g_edge[e]);
            uint2 r1 = __ldg(&g_edge[e + 1]);
            uint2 r2 = __ldg(&g_edge[e + 2]);
            uint2 r3 = __ldg(&g_edge[e + 3]);
            uint2 u0 = __ldg(&Hm[(size_t)(r0.x & 0x1FFFFu) * 32 + lane]);
            uint2 u1 = __ldg(&Hm[(size_t)(r1.x & 0x1FFFFu) * 32 + lane]);
            uint2 u2 = __ldg(&Hm[(size_t)(r2.x & 0x1FFFFu) * 32 + lane]);
            uint2 u3 = __ldg(&Hm[(size_t)(r3.x & 0x1FFFFu) * 32 + lane]);
            fma_row(u0, dv * __uint_as_float(r0.y), nx, ny, nz, nw);
            fma_row(u1, dv * __uint_as_float(r1.y), nx, ny, nz, nw);
            fma_row(u2, dv * __uint_as_float(r2.y), nx, ny, nz, nw);
            fma_row(u3, dv * __uint_as_float(r3.y), nx, ny, nz, nw);
        }
        for (; e < e1; e++) {
            uint2 r0 = __ldg(&g_edge[e]);
            uint2 u0 = __ldg(&Hm[(size_t)(r0.x & 0x1FFFFu) * 32 + lane]);
            fma_row(u0, dv * __uint_as_float(r0.y), nx, ny, nz, nw);
        }
        int g = batch[v];
        if (g != curg) {
            if (curg >= 0) {
                float* p = g_gsum + curg * H + lane * 4;
                atomicAdd(p, gx); atomicAdd(p + 1, gy);
                atomicAdd(p + 2, gz); atomicAdd(p + 3, gwv);
            }
            curg = g; gx = nx; gy = ny; gz = nz; gwv = nw;
        } else {
            gx += nx; gy += ny; gz += nz; gwv += nw;
        }
    }
    if (curg >= 0) {
        float* p = g_gsum + curg * H + lane * 4;
        atomicAdd(p, gx); atomicAdd(p + 1, gy);
        atomicAdd(p + 2, gz); atomicAdd(p + 3, gwv);
    }
}

// ---- final: out[g] = (gsum[g] @ W2) / cnt[g] + b2 ; re-zeroes gsum/gcnt ----
__global__ void k_final(const float* __restrict__ W2, const float* __restrict__ b2,
                        float* __restrict__ out) {
    __shared__ float srow[H];
    int g = blockIdx.x, j = threadIdx.x;
    srow[j] = g_gsum[g * H + j];
    int c = g_gcnt[g];
    __syncthreads();
    g_gsum[g * H + j] = 0.f;          // re-zero for next replay
    if (j == 0) g_gcnt[g] = 0;
    float acc = 0.f;
#pragma unroll 8
    for (int k = 0; k < H; k++) acc = fmaf(srow[k], W2[k * H + j], acc);
    out[g * H + j] = (c > 0) ? (acc / (float)c + b2[j]) : 0.f;
}

extern "C" void kernel_launch(void* const* d_in, const int* in_sizes, int n_in,
                              void* d_out, int out_size) {
    const int*   x     = (const int*)d_in[0];
    const int*   ei    = (const int*)d_in[1];
    const int*   batch = (const int*)d_in[2];
    const float* emb   = (const float*)d_in[3];
    const float* W1    = (const float*)d_in[4];
    const float* b1    = (const float*)d_in[5];
    const float* W2    = (const float*)d_in[6];
    const float* b2    = (const float*)d_in[7];
    float* out = (float*)d_out;

    int N = in_sizes[0];
    int E = in_sizes[1] / 2;
    const int* src = ei;
    const int* dst = ei + E;

    k_prepcount<<<1024, 128>>>(emb, W1, dst, E, batch, N);
    int nb = (N + 1023) / 1024;
    k_scanA<<<nb, 1024>>>(N);
    k_scanC<<<nb, 1024>>>(N, E);
    k_fill<<<(E + 255) / 256, 256>>>(src, dst, x, E);
    k_conv1<<<((size_t)N * 32 + 255) / 256, 256>>>(x, b1, N);
    int w2n = (N + 15) / 16;
    k_conv2pool<<<((size_t)w2n * 32 + 255) / 256, 256>>>(batch, N);
    k_final<<<NG, H>>>(W2, b2, out);
}